// round 15
// baseline (speedup 1.0000x reference)
#include <cuda_runtime.h>
#include <cuda_bf16.h>
#include <math.h>
#include <stdint.h>

#define BATCH 8
#define CH 128
#define NTOK 4096
#define NGRP 32
#define CPG 4
#define GN_EPS 1e-5f
#define QK_SCALE_L2E 0.12751748754f   // log2(e)/sqrt(128)

// ---------------- scratch (device globals; no allocations) ----------------
__device__ float2 g_stats[BATCH * NGRP];             // (mean, rstd) per (b,g)
__device__ __nv_bfloat16 g_k[BATCH * NTOK * CH];     // (b,n,c) token-major
__device__ __nv_bfloat16 g_v[BATCH * CH * NTOK];     // (b,c,n) channel-major (V^T tiles)
__device__ int g_cnt[BATCH];                         // kv-done counters (zeroed by gn_stats)
// pre-packed weights, bf16 [o][136 halfwords] = 68 u32/row, 8704 u32 = 34816 B each
__device__ uint32_t g_wq_pk[8704];
__device__ uint32_t g_wk_pk[8704];
__device__ uint32_t g_wv_pk[8704];
__device__ uint32_t g_wo_pk[8704];

// ======================= helpers =======================
__device__ __forceinline__ uint32_t smem_u32(const void* p) {
    uint32_t a;
    asm("{ .reg .u64 t; cvta.to.shared.u64 t, %1; cvt.u32.u64 %0, t; }" : "=r"(a) : "l"(p));
    return a;
}
__device__ __forceinline__ uint32_t pack_bf16x2(float lo, float hi) {
    uint32_t r;
    asm("cvt.rn.bf16x2.f32 %0, %1, %2;" : "=r"(r) : "f"(hi), "f"(lo));
    return r;
}
// D += A*B, m16n8k16, bf16 in / fp32 accum. A row-major m16xk16, B col-major k16xn8.
__device__ __forceinline__ void mma_bf16(float* d, uint32_t a0, uint32_t a1, uint32_t a2, uint32_t a3,
                                         uint32_t b0, uint32_t b1) {
    asm volatile(
        "mma.sync.aligned.m16n8k16.row.col.f32.bf16.bf16.f32 "
        "{%0,%1,%2,%3}, {%4,%5,%6,%7}, {%8,%9}, {%0,%1,%2,%3};"
        : "+f"(d[0]), "+f"(d[1]), "+f"(d[2]), "+f"(d[3])
        : "r"(a0), "r"(a1), "r"(a2), "r"(a3), "r"(b0), "r"(b1));
}
#define LDSM_X4(r0, r1, r2, r3, addr) \
    asm volatile("ldmatrix.sync.aligned.m8n8.x4.shared.b16 {%0,%1,%2,%3}, [%4];" \
                 : "=r"(r0), "=r"(r1), "=r"(r2), "=r"(r3) : "r"(addr))
#define CP_ASYNC16(dst_u32, src_ptr) \
    asm volatile("cp.async.cg.shared.global [%0], [%1], 16;" :: "r"(dst_u32), "l"(src_ptr))
#define CP_COMMIT()  asm volatile("cp.async.commit_group;" ::: "memory")
#define CP_WAIT1()   asm volatile("cp.async.wait_group 1;" ::: "memory")
#define CP_WAIT0()   asm volatile("cp.async.wait_group 0;" ::: "memory")

// ======================= K1: GroupNorm stats + counter reset + W packing =======================
__global__ __launch_bounds__(512) void gn_stats_kernel(const float* __restrict__ x,
                                                       const float* __restrict__ wq,
                                                       const float* __restrict__ wk,
                                                       const float* __restrict__ wv,
                                                       const float* __restrict__ wo) {
    int bg = blockIdx.x;
    if (bg >= BATCH * NGRP) {
        // W packing blocks
        int which = bg - BATCH * NGRP;
        const float* W = (which == 0) ? wq : (which == 1) ? wk : (which == 2) ? wv : wo;
        uint32_t* dst = (which == 0) ? g_wq_pk : (which == 1) ? g_wk_pk : (which == 2) ? g_wv_pk : g_wo_pk;
#pragma unroll
        for (int r = 0; r < 17; r++) {
            int idx = threadIdx.x + r * 512;     // 8704 = 512*17
            int o = idx / 68, s = idx % 68;
            dst[idx] = (s < 64) ? pack_bf16x2(W[o * 128 + 2 * s], W[o * 128 + 2 * s + 1]) : 0u;
        }
        return;
    }
    if (threadIdx.x == 0 && bg < BATCH) g_cnt[bg] = 0;
    size_t base = (size_t)bg * CPG * NTOK;
    const float4* xv = (const float4*)(x + base);
    int tid = threadIdx.x;

    float s = 0.f, ss = 0.f;
#pragma unroll
    for (int r = 0; r < 8; r++) {
        float4 v = xv[tid + r * 512];
        s  += v.x + v.y + v.z + v.w;
        ss += v.x * v.x + v.y * v.y + v.z * v.z + v.w * v.w;
    }
    __shared__ float rs[16], rss[16];
#pragma unroll
    for (int o = 16; o; o >>= 1) {
        s  += __shfl_xor_sync(0xffffffffu, s, o);
        ss += __shfl_xor_sync(0xffffffffu, ss, o);
    }
    if ((tid & 31) == 0) { rs[tid >> 5] = s; rss[tid >> 5] = ss; }
    __syncthreads();
    if (tid == 0) {
        float ts = 0.f, tss = 0.f;
#pragma unroll
        for (int i = 0; i < 16; i++) { ts += rs[i]; tss += rss[i]; }
        const float invN = 1.f / (CPG * NTOK);
        float mean = ts * invN;
        float var  = tss * invN - mean * mean;
        g_stats[bg] = make_float2(mean, rsqrtf(var + GN_EPS));
    }
}

// ======================= K2: mega kernel, 128 threads, M=32 per warp =======================
#define PA_XS 0
#define PA_WS 34816
#define PA_STG 69632
#define KT 17408                               // K tile [64 key][136 bf16]
#define VT 18432                               // V^T tile [128 ch][72 bf16]
#define OFF_KB(i) ((i) * KT)
#define OFF_VB(i) (3 * KT + (i) * VT)
#define OFF_WO 17408                           // epilogue Wo image: KB(1)+KB(2) = 17408..52224
#define ATTN_SMEM (3 * KT + 3 * VT)            // 107520 B -> 2 CTA/SM

__global__ __launch_bounds__(128, 2) void mega_kernel(
        const float* __restrict__ x,
        const float* __restrict__ gw, const float* __restrict__ gb,
        const float* __restrict__ bq, const float* __restrict__ bk,
        const float* __restrict__ bv, const float* __restrict__ bo,
        const float* __restrict__ gamma, float* __restrict__ out) {
    extern __shared__ char smem[];
    uint32_t sbase = smem_u32(smem);
    int tid = threadIdx.x;
    int w = tid >> 5, lid = tid & 31;
    int gr = lid >> 2, t = lid & 3;
    int r0 = w * 32;                 // 32 q-rows / output-channels per warp (2 m16 blocks)
    int b = blockIdx.y, n0 = blockIdx.x * 128;
    int own = blockIdx.x * 2;        // first 64-key tile this CTA produced

    __nv_bfloat16* xs_h = (__nv_bfloat16*)(smem + PA_XS);
    uint4* ws_v4 = (uint4*)(smem + PA_WS);

    const __nv_bfloat16* kg = g_k + (size_t)b * NTOK * CH;
    const __nv_bfloat16* vg = g_v + (size_t)b * CH * NTOK;
    int kload_row = tid >> 4, kload_seg = tid & 15;
    int vload_row = tid >> 3, vload_seg = tid & 7;

    // ======== Phase A1: stage x-hat once + copy pre-packed Wk ========
#pragma unroll
    for (int r = 0; r < 32; r++) {
        int idx = tid + r * 128;
        int c = idx >> 5, seg = idx & 31;
        float4 v = *(const float4*)&x[((size_t)(b * CH + c)) * NTOK + n0 + seg * 4];
        float2 st = g_stats[b * NGRP + (c >> 2)];
        float a = gw[c] * st.y;
        float bb = gb[c] - st.x * a;
        int tok = seg * 4;
        xs_h[(tok + 0) * 136 + c] = __float2bfloat16(v.x * a + bb);
        xs_h[(tok + 1) * 136 + c] = __float2bfloat16(v.y * a + bb);
        xs_h[(tok + 2) * 136 + c] = __float2bfloat16(v.z * a + bb);
        xs_h[(tok + 3) * 136 + c] = __float2bfloat16(v.w * a + bb);
    }
#pragma unroll
    for (int r = 0; r < 17; r++) {
        int idx = tid + r * 128;             // 2176 uint4 = 34816 B
        ws_v4[idx] = ((const uint4*)g_wk_pk)[idx];
    }
    __syncthreads();

    uint32_t bbase = sbase + PA_XS + (uint32_t)(lid & 7) * 272 + (uint32_t)(lid >> 3) * 16;
    uint32_t abw0 = sbase + PA_WS + (uint32_t)(r0 + (lid & 15)) * 272 + (uint32_t)(lid >> 4) * 16;
    uint32_t abw1 = abw0 + 16 * 272;

    // ======== Phase A2: K projection (two m16 o-blocks per warp) ========
    {
        uint32_t af[2][8][4];
#pragma unroll
        for (int c = 0; c < 8; c++) {
            LDSM_X4(af[0][c][0], af[0][c][1], af[0][c][2], af[0][c][3], abw0 + c * 32);
            LDSM_X4(af[1][c][0], af[1][c][1], af[1][c][2], af[1][c][3], abw1 + c * 32);
        }
        float bs0 = bk[r0 + gr],      bs1 = bk[r0 + 8 + gr];
        float bs2 = bk[r0 + 16 + gr], bs3 = bk[r0 + 24 + gr];
        __nv_bfloat16* stg = (__nv_bfloat16*)(smem + PA_STG);
#pragma unroll 2
        for (int nb = 0; nb < 16; nb++) {
            float d0[4] = {0.f, 0.f, 0.f, 0.f};
            float d1[4] = {0.f, 0.f, 0.f, 0.f};
#pragma unroll
            for (int cp = 0; cp < 4; cp++) {
                uint32_t b0, b1, b2, b3;
                LDSM_X4(b0, b1, b2, b3, bbase + (uint32_t)nb * 2176 + cp * 64);
                mma_bf16(d0, af[0][2 * cp][0], af[0][2 * cp][1], af[0][2 * cp][2], af[0][2 * cp][3], b0, b1);
                mma_bf16(d1, af[1][2 * cp][0], af[1][2 * cp][1], af[1][2 * cp][2], af[1][2 * cp][3], b0, b1);
                mma_bf16(d0, af[0][2 * cp + 1][0], af[0][2 * cp + 1][1], af[0][2 * cp + 1][2], af[0][2 * cp + 1][3], b2, b3);
                mma_bf16(d1, af[1][2 * cp + 1][0], af[1][2 * cp + 1][1], af[1][2 * cp + 1][2], af[1][2 * cp + 1][3], b2, b3);
            }
            int tok = nb * 8 + 2 * t;
            stg[tok * 136 + r0 + gr]            = __float2bfloat16(d0[0] + bs0);
            stg[(tok + 1) * 136 + r0 + gr]      = __float2bfloat16(d0[1] + bs0);
            stg[tok * 136 + r0 + 8 + gr]        = __float2bfloat16(d0[2] + bs1);
            stg[(tok + 1) * 136 + r0 + 8 + gr]  = __float2bfloat16(d0[3] + bs1);
            stg[tok * 136 + r0 + 16 + gr]       = __float2bfloat16(d1[0] + bs2);
            stg[(tok + 1) * 136 + r0 + 16 + gr] = __float2bfloat16(d1[1] + bs2);
            stg[tok * 136 + r0 + 24 + gr]       = __float2bfloat16(d1[2] + bs3);
            stg[(tok + 1) * 136 + r0 + 24 + gr] = __float2bfloat16(d1[3] + bs3);
        }
        __syncthreads();
#pragma unroll
        for (int r = 0; r < 16; r++) {
            int idx = tid + r * 128;
            int tok = idx >> 4, seg = idx & 15;
            uint4 v = *(uint4*)(smem + PA_STG + tok * 272 + seg * 16);
            *(uint4*)((char*)g_k + ((size_t)b * NTOK + n0 + tok) * 256 + seg * 16) = v;
        }
#pragma unroll
        for (int r = 0; r < 17; r++) {
            int idx = tid + r * 128;
            ws_v4[idx] = ((const uint4*)g_wv_pk)[idx];
        }
        __syncthreads();
    }

    // ======== Phase A3: V projection ========
    {
        uint32_t af[2][8][4];
#pragma unroll
        for (int c = 0; c < 8; c++) {
            LDSM_X4(af[0][c][0], af[0][c][1], af[0][c][2], af[0][c][3], abw0 + c * 32);
            LDSM_X4(af[1][c][0], af[1][c][1], af[1][c][2], af[1][c][3], abw1 + c * 32);
        }
        float bs0 = bv[r0 + gr],      bs1 = bv[r0 + 8 + gr];
        float bs2 = bv[r0 + 16 + gr], bs3 = bv[r0 + 24 + gr];
        uint32_t* stg = (uint32_t*)(smem + PA_STG);
#pragma unroll 2
        for (int nb = 0; nb < 16; nb++) {
            float d0[4] = {0.f, 0.f, 0.f, 0.f};
            float d1[4] = {0.f, 0.f, 0.f, 0.f};
#pragma unroll
            for (int cp = 0; cp < 4; cp++) {
                uint32_t b0, b1, b2, b3;
                LDSM_X4(b0, b1, b2, b3, bbase + (uint32_t)nb * 2176 + cp * 64);
                mma_bf16(d0, af[0][2 * cp][0], af[0][2 * cp][1], af[0][2 * cp][2], af[0][2 * cp][3], b0, b1);
                mma_bf16(d1, af[1][2 * cp][0], af[1][2 * cp][1], af[1][2 * cp][2], af[1][2 * cp][3], b0, b1);
                mma_bf16(d0, af[0][2 * cp + 1][0], af[0][2 * cp + 1][1], af[0][2 * cp + 1][2], af[0][2 * cp + 1][3], b2, b3);
                mma_bf16(d1, af[1][2 * cp + 1][0], af[1][2 * cp + 1][1], af[1][2 * cp + 1][2], af[1][2 * cp + 1][3], b2, b3);
            }
            stg[(r0 + gr) * 68 + nb * 4 + t]      = pack_bf16x2(d0[0] + bs0, d0[1] + bs0);
            stg[(r0 + 8 + gr) * 68 + nb * 4 + t]  = pack_bf16x2(d0[2] + bs1, d0[3] + bs1);
            stg[(r0 + 16 + gr) * 68 + nb * 4 + t] = pack_bf16x2(d1[0] + bs2, d1[1] + bs2);
            stg[(r0 + 24 + gr) * 68 + nb * 4 + t] = pack_bf16x2(d1[2] + bs3, d1[3] + bs3);
        }
        __syncthreads();
#pragma unroll
        for (int r = 0; r < 16; r++) {
            int idx = tid + r * 128;
            int c = idx >> 4, seg = idx & 15;
            uint4 v = *(uint4*)(smem + PA_STG + c * 272 + seg * 16);
            *(uint4*)((char*)g_v + (((size_t)(b * CH + c)) * NTOK + n0) * 2 + seg * 16) = v;
        }
#pragma unroll
        for (int r = 0; r < 17; r++) {
            int idx = tid + r * 128;
            ws_v4[idx] = ((const uint4*)g_wq_pk)[idx];
        }
        __threadfence();
        __syncthreads();
        if (tid == 0) atomicAdd(&g_cnt[b], 1);   // release K/V for this tile
    }

    // ======== Phase A4: Q projection (overlaps peers' KV work) ========
    uint32_t qa[2][8][4];
    {
        uint32_t wqb = sbase + PA_WS + (uint32_t)(lid & 7) * 272 + (uint32_t)(lid >> 3) * 16;
#pragma unroll
        for (int blk = 0; blk < 2; blk++) {
            uint32_t xa[8][4];
            uint32_t abx = sbase + PA_XS + (uint32_t)(r0 + blk * 16 + (lid & 15)) * 272 + (uint32_t)(lid >> 4) * 16;
#pragma unroll
            for (int c = 0; c < 8; c++)
                LDSM_X4(xa[c][0], xa[c][1], xa[c][2], xa[c][3], abx + c * 32);
#pragma unroll
            for (int k = 0; k < 8; k++) {
#pragma unroll
                for (int half = 0; half < 2; half++) {
                    int nb = 2 * k + half;
                    float d[4] = {0.f, 0.f, 0.f, 0.f};
#pragma unroll
                    for (int cp = 0; cp < 4; cp++) {
                        uint32_t b0, b1, b2, b3;
                        LDSM_X4(b0, b1, b2, b3, wqb + (uint32_t)nb * 2176 + cp * 64);
                        mma_bf16(d, xa[2 * cp][0], xa[2 * cp][1], xa[2 * cp][2], xa[2 * cp][3], b0, b1);
                        mma_bf16(d, xa[2 * cp + 1][0], xa[2 * cp + 1][1], xa[2 * cp + 1][2], xa[2 * cp + 1][3], b2, b3);
                    }
                    float2 bq2 = *(const float2*)&bq[nb * 8 + 2 * t];
                    qa[blk][k][2 * half]     = pack_bf16x2((d[0] + bq2.x) * QK_SCALE_L2E, (d[1] + bq2.y) * QK_SCALE_L2E);
                    qa[blk][k][2 * half + 1] = pack_bf16x2((d[2] + bq2.x) * QK_SCALE_L2E, (d[3] + bq2.y) * QK_SCALE_L2E);
                }
            }
        }
    }

    // ======== Phase A5: wait for batch KV completion ========
    if (tid == 0) {
        while (atomicAdd(&g_cnt[b], 0) < NTOK / 128) { }
    }
    __syncthreads();    // phase A smem dead only after this point

    // ======== ring prefetch: rotated start at own tiles ========
#pragma unroll
    for (int pt = 0; pt < 2; pt++) {
        int gt = own + pt;
        const char* kn = (const char*)kg + (size_t)gt * 64 * 256;
        const char* vn = (const char*)vg + (size_t)gt * 128;
        uint32_t koff = sbase + OFF_KB(pt);
        uint32_t voff = sbase + OFF_VB(pt);
#pragma unroll
        for (int r = 0; r < 8; r++) {
            int row = kload_row + r * 8;
            CP_ASYNC16(koff + row * 272 + kload_seg * 16, kn + row * 256 + kload_seg * 16);
        }
#pragma unroll
        for (int r = 0; r < 8; r++) {
            int row = vload_row + r * 16;
            CP_ASYNC16(voff + row * 144 + vload_seg * 16, vn + (size_t)row * NTOK * 2 + vload_seg * 16);
        }
        CP_COMMIT();
    }

    // ======== Phase B: flash attention mainloop (rotated tile order) ========
    float oacc[2][16][4];
#pragma unroll
    for (int blk = 0; blk < 2; blk++)
#pragma unroll
        for (int v = 0; v < 16; v++)
#pragma unroll
            for (int i = 0; i < 4; i++) oacc[blk][v][i] = 0.f;
    float l0[2] = {0.f, 0.f}, l1[2] = {0.f, 0.f};

    uint32_t klane = (uint32_t)(lid & 7) * 272 + (uint32_t)(lid >> 3) * 16;
    uint32_t vlane = (uint32_t)(lid & 7) * 144 + (uint32_t)(lid >> 3) * 16;

    int cur = 0, pre = 2;
    for (int tl = 0; tl < NTOK / 64; tl++) {
        CP_WAIT1();
        __syncthreads();

        if (tl + 2 < NTOK / 64) {
            int gt2 = (own + tl + 2) & 63;
            const char* kn = (const char*)kg + (size_t)gt2 * 64 * 256;
            const char* vn = (const char*)vg + (size_t)gt2 * 128;
            uint32_t koff = sbase + OFF_KB(pre);
            uint32_t voff = sbase + OFF_VB(pre);
#pragma unroll
            for (int r = 0; r < 8; r++) {
                int row = kload_row + r * 8;
                CP_ASYNC16(koff + row * 272 + kload_seg * 16, kn + row * 256 + kload_seg * 16);
            }
#pragma unroll
            for (int r = 0; r < 8; r++) {
                int row = vload_row + r * 16;
                CP_ASYNC16(voff + row * 144 + vload_seg * 16, vn + (size_t)row * NTOK * 2 + vload_seg * 16);
            }
        } else if (tl == NTOK / 64 - 1) {
            // last tile: prefetch pre-packed Wo into dead ring slots KB(1)+KB(2)
            // (KB(1) free since tl-2 barrier, KB(2) free since previous barrier; this tile reads KB(0)/VB(0) only)
#pragma unroll
            for (int r = 0; r < 17; r++) {
                int idx = tid + r * 128;          // 2176 chunks x 16 B = 34816 B
                CP_ASYNC16(sbase + OFF_WO + idx * 16, (const char*)g_wo_pk + idx * 16);
            }
        }
        CP_COMMIT();

        uint32_t kb = sbase + OFF_KB(cur) + klane;
        uint32_t vb = sbase + OFF_VB(cur) + vlane;

        // half-interleaved: QK for 4 n-blocks, then PV for matching 32 keys
#pragma unroll
        for (int half = 0; half < 2; half++) {
            uint32_t epk[2][4][2];
#pragma unroll
            for (int nn = 0; nn < 4; nn++) {
                int n = half * 4 + nn;
                float s0[4] = {0.f, 0.f, 0.f, 0.f};
                float s1[4] = {0.f, 0.f, 0.f, 0.f};
                uint32_t krow = kb + (uint32_t)n * 2176;
#pragma unroll
                for (int cp = 0; cp < 4; cp++) {
                    uint32_t b0, b1, b2, b3;
                    LDSM_X4(b0, b1, b2, b3, krow + cp * 64);
                    mma_bf16(s0, qa[0][2 * cp][0], qa[0][2 * cp][1], qa[0][2 * cp][2], qa[0][2 * cp][3], b0, b1);
                    mma_bf16(s1, qa[1][2 * cp][0], qa[1][2 * cp][1], qa[1][2 * cp][2], qa[1][2 * cp][3], b0, b1);
                    mma_bf16(s0, qa[0][2 * cp + 1][0], qa[0][2 * cp + 1][1], qa[0][2 * cp + 1][2], qa[0][2 * cp + 1][3], b2, b3);
                    mma_bf16(s1, qa[1][2 * cp + 1][0], qa[1][2 * cp + 1][1], qa[1][2 * cp + 1][2], qa[1][2 * cp + 1][3], b2, b3);
                }
                float e00 = exp2f(s0[0]), e01 = exp2f(s0[1]);
                float e02 = exp2f(s0[2]), e03 = exp2f(s0[3]);
                float e10 = exp2f(s1[0]), e11 = exp2f(s1[1]);
                float e12 = exp2f(s1[2]), e13 = exp2f(s1[3]);
                l0[0] += e00 + e01; l1[0] += e02 + e03;
                l0[1] += e10 + e11; l1[1] += e12 + e13;
                epk[0][nn][0] = pack_bf16x2(e00, e01);
                epk[0][nn][1] = pack_bf16x2(e02, e03);
                epk[1][nn][0] = pack_bf16x2(e10, e11);
                epk[1][nn][1] = pack_bf16x2(e12, e13);
            }
#pragma unroll
            for (int v = 0; v < 16; v++) {
                uint32_t b0, b1, b2, b3;
                LDSM_X4(b0, b1, b2, b3, vb + (uint32_t)v * 1152 + half * 64);
                mma_bf16(oacc[0][v], epk[0][0][0], epk[0][0][1], epk[0][1][0], epk[0][1][1], b0, b1);
                mma_bf16(oacc[1][v], epk[1][0][0], epk[1][0][1], epk[1][1][0], epk[1][1][1], b0, b1);
                mma_bf16(oacc[0][v], epk[0][2][0], epk[0][2][1], epk[0][3][0], epk[0][3][1], b2, b3);
                mma_bf16(oacc[1][v], epk[1][2][0], epk[1][2][1], epk[1][3][0], epk[1][3][1], b2, b3);
            }
        }

        cur = (cur == 2) ? 0 : cur + 1;
        pre = (pre == 2) ? 0 : pre + 1;
    }

    // ---- row sums ----
#pragma unroll
    for (int blk = 0; blk < 2; blk++) {
        l0[blk] += __shfl_xor_sync(0xffffffffu, l0[blk], 1);
        l0[blk] += __shfl_xor_sync(0xffffffffu, l0[blk], 2);
        l1[blk] += __shfl_xor_sync(0xffffffffu, l1[blk], 1);
        l1[blk] += __shfl_xor_sync(0xffffffffu, l1[blk], 2);
    }

    // ======== fused output projection epilogue (Wo already in smem via cp.async) ========
    uint32_t af[2][8][4];
#pragma unroll
    for (int blk = 0; blk < 2; blk++) {
        float inv0 = 1.f / l0[blk], inv1 = 1.f / l1[blk];
#pragma unroll
        for (int cp = 0; cp < 8; cp++) {
            af[blk][cp][0] = pack_bf16x2(oacc[blk][2 * cp][0] * inv0,     oacc[blk][2 * cp][1] * inv0);
            af[blk][cp][1] = pack_bf16x2(oacc[blk][2 * cp][2] * inv1,     oacc[blk][2 * cp][3] * inv1);
            af[blk][cp][2] = pack_bf16x2(oacc[blk][2 * cp + 1][0] * inv0, oacc[blk][2 * cp + 1][1] * inv0);
            af[blk][cp][3] = pack_bf16x2(oacc[blk][2 * cp + 1][2] * inv1, oacc[blk][2 * cp + 1][3] * inv1);
        }
    }

    CP_WAIT0();        // Wo image landed
    __syncthreads();   // all warps past ring reads; Wo visible block-wide

    __nv_bfloat16* stg = (__nv_bfloat16*)(smem + OFF_VB(0));
    uint32_t wob = sbase + OFF_WO + klane;
#pragma unroll 2
    for (int nb = 0; nb < 16; nb++) {
        float d0[4] = {0.f, 0.f, 0.f, 0.f};
        float d1[4] = {0.f, 0.f, 0.f, 0.f};
#pragma unroll
        for (int cp = 0; cp < 4; cp++) {
            uint32_t b0, b1, b2, b3;
            LDSM_X4(b0, b1, b2, b3, wob + (uint32_t)nb * 2176 + cp * 64);
            mma_bf16(d0, af[0][2 * cp][0], af[0][2 * cp][1], af[0][2 * cp][2], af[0][2 * cp][3], b0, b1);
            mma_bf16(d1, af[1][2 * cp][0], af[1][2 * cp][1], af[1][2 * cp][2], af[1][2 * cp][3], b0, b1);
            mma_bf16(d0, af[0][2 * cp + 1][0], af[0][2 * cp + 1][1], af[0][2 * cp + 1][2], af[0][2 * cp + 1][3], b2, b3);
            mma_bf16(d1, af[1][2 * cp + 1][0], af[1][2 * cp + 1][1], af[1][2 * cp + 1][2], af[1][2 * cp + 1][3], b2, b3);
        }
        int o = nb * 8 + 2 * t;
        stg[o * 136 + r0 + gr]            = __float2bfloat16(d0[0]);
        stg[(o + 1) * 136 + r0 + gr]      = __float2bfloat16(d0[1]);
        stg[o * 136 + r0 + 8 + gr]        = __float2bfloat16(d0[2]);
        stg[(o + 1) * 136 + r0 + 8 + gr]  = __float2bfloat16(d0[3]);
        stg[o * 136 + r0 + 16 + gr]       = __float2bfloat16(d1[0]);
        stg[(o + 1) * 136 + r0 + 16 + gr] = __float2bfloat16(d1[1]);
        stg[o * 136 + r0 + 24 + gr]       = __float2bfloat16(d1[2]);
        stg[(o + 1) * 136 + r0 + 24 + gr] = __float2bfloat16(d1[3]);
    }
    __syncthreads();

    float gma = gamma[0];
#pragma unroll
    for (int r = 0; r < 16; r++) {
        int idx = tid + r * 128;
        int o = idx >> 4, seg = idx & 15;
        uint4 pv = *(uint4*)((char*)stg + o * 272 + seg * 16);
        float bv_ = bo[o];
        size_t gidx = ((size_t)(b * CH + o)) * NTOK + n0 + seg * 8;
        float4 x0 = *(const float4*)&x[gidx];
        float4 x1 = *(const float4*)&x[gidx + 4];
        float2 u0 = __bfloat1622float2(*(__nv_bfloat162*)&pv.x);
        float2 u1 = __bfloat1622float2(*(__nv_bfloat162*)&pv.y);
        float2 u2 = __bfloat1622float2(*(__nv_bfloat162*)&pv.z);
        float2 u3 = __bfloat1622float2(*(__nv_bfloat162*)&pv.w);
        float4 o0, o1;
        o0.x = x0.x + gma * (u0.x + bv_);
        o0.y = x0.y + gma * (u0.y + bv_);
        o0.z = x0.z + gma * (u1.x + bv_);
        o0.w = x0.w + gma * (u1.y + bv_);
        o1.x = x1.x + gma * (u2.x + bv_);
        o1.y = x1.y + gma * (u2.y + bv_);
        o1.z = x1.z + gma * (u3.x + bv_);
        o1.w = x1.w + gma * (u3.y + bv_);
        *(float4*)&out[gidx] = o0;
        *(float4*)&out[gidx + 4] = o1;
    }
}

// ======================= launch =======================
extern "C" void kernel_launch(void* const* d_in, const int* in_sizes, int n_in,
                              void* d_out, int out_size) {
    const float* x  = (const float*)d_in[0];
    const float* gw = (const float*)d_in[1];
    const float* gb = (const float*)d_in[2];
    const float* wq = (const float*)d_in[3];
    const float* bq = (const float*)d_in[4];
    const float* wk = (const float*)d_in[5];
    const float* bk = (const float*)d_in[6];
    const float* wv = (const float*)d_in[7];
    const float* bv = (const float*)d_in[8];
    const float* wo = (const float*)d_in[9];
    const float* bo = (const float*)d_in[10];
    const float* gamma = (const float*)d_in[11];
    float* out = (float*)d_out;

    static bool attr_set = false;
    if (!attr_set) {
        cudaFuncSetAttribute(mega_kernel, cudaFuncAttributeMaxDynamicSharedMemorySize, ATTN_SMEM);
        attr_set = true;
    }

    gn_stats_kernel<<<BATCH * NGRP + 4, 512>>>(x, wq, wk, wv, wo);
    mega_kernel<<<dim3(NTOK / 128, BATCH), 128, ATTN_SMEM>>>(
        x, gw, gb, bq, bk, bv, bo, gamma, out);
}

// round 16
// speedup vs baseline: 1.0071x; 1.0071x over previous
#include <cuda_runtime.h>
#include <cuda_bf16.h>
#include <math.h>
#include <stdint.h>

#define BATCH 8
#define CH 128
#define NTOK 4096
#define NGRP 32
#define CPG 4
#define GN_EPS 1e-5f
#define QK_SCALE_L2E 0.12751748754f   // log2(e)/sqrt(128)

// ---------------- scratch (device globals; no allocations) ----------------
__device__ float2 g_stats[BATCH * NGRP];             // (mean, rstd) per (b,g)
__device__ __nv_bfloat16 g_k[BATCH * NTOK * CH];     // (b,n,c) token-major
__device__ __nv_bfloat16 g_v[BATCH * CH * NTOK];     // (b,c,n) channel-major (V^T tiles)
__device__ int g_cnt[BATCH];                         // kv-done counters (zeroed by gn_stats)
// pre-packed weights, bf16 [o][136 halfwords] = 68 u32/row, 8704 u32 = 34816 B each
__device__ uint32_t g_wq_pk[8704];
__device__ uint32_t g_wk_pk[8704];
__device__ uint32_t g_wv_pk[8704];
__device__ uint32_t g_wo_pk[8704];

// ======================= helpers =======================
__device__ __forceinline__ uint32_t smem_u32(const void* p) {
    uint32_t a;
    asm("{ .reg .u64 t; cvta.to.shared.u64 t, %1; cvt.u32.u64 %0, t; }" : "=r"(a) : "l"(p));
    return a;
}
__device__ __forceinline__ uint32_t pack_bf16x2(float lo, float hi) {
    uint32_t r;
    asm("cvt.rn.bf16x2.f32 %0, %1, %2;" : "=r"(r) : "f"(hi), "f"(lo));
    return r;
}
__device__ __forceinline__ float ex2_fast(float x) {
    float r;
    asm("ex2.approx.ftz.f32 %0, %1;" : "=f"(r) : "f"(x));
    return r;
}
// D += A*B, m16n8k16, bf16 in / fp32 accum. A row-major m16xk16, B col-major k16xn8.
__device__ __forceinline__ void mma_bf16(float* d, uint32_t a0, uint32_t a1, uint32_t a2, uint32_t a3,
                                         uint32_t b0, uint32_t b1) {
    asm volatile(
        "mma.sync.aligned.m16n8k16.row.col.f32.bf16.bf16.f32 "
        "{%0,%1,%2,%3}, {%4,%5,%6,%7}, {%8,%9}, {%0,%1,%2,%3};"
        : "+f"(d[0]), "+f"(d[1]), "+f"(d[2]), "+f"(d[3])
        : "r"(a0), "r"(a1), "r"(a2), "r"(a3), "r"(b0), "r"(b1));
}
#define LDSM_X4(r0, r1, r2, r3, addr) \
    asm volatile("ldmatrix.sync.aligned.m8n8.x4.shared.b16 {%0,%1,%2,%3}, [%4];" \
                 : "=r"(r0), "=r"(r1), "=r"(r2), "=r"(r3) : "r"(addr))
#define CP_ASYNC16(dst_u32, src_ptr) \
    asm volatile("cp.async.cg.shared.global [%0], [%1], 16;" :: "r"(dst_u32), "l"(src_ptr))
#define CP_COMMIT()  asm volatile("cp.async.commit_group;" ::: "memory")
#define CP_WAIT1()   asm volatile("cp.async.wait_group 1;" ::: "memory")
#define CP_WAIT0()   asm volatile("cp.async.wait_group 0;" ::: "memory")

// ======================= K1: GroupNorm stats + counter reset + W packing =======================
__global__ __launch_bounds__(512) void gn_stats_kernel(const float* __restrict__ x,
                                                       const float* __restrict__ wq,
                                                       const float* __restrict__ wk,
                                                       const float* __restrict__ wv,
                                                       const float* __restrict__ wo) {
    int bg = blockIdx.x;
    if (bg >= BATCH * NGRP) {
        int which = bg - BATCH * NGRP;
        const float* W = (which == 0) ? wq : (which == 1) ? wk : (which == 2) ? wv : wo;
        uint32_t* dst = (which == 0) ? g_wq_pk : (which == 1) ? g_wk_pk : (which == 2) ? g_wv_pk : g_wo_pk;
#pragma unroll
        for (int r = 0; r < 17; r++) {
            int idx = threadIdx.x + r * 512;
            int o = idx / 68, s = idx % 68;
            dst[idx] = (s < 64) ? pack_bf16x2(W[o * 128 + 2 * s], W[o * 128 + 2 * s + 1]) : 0u;
        }
        return;
    }
    if (threadIdx.x == 0 && bg < BATCH) g_cnt[bg] = 0;
    size_t base = (size_t)bg * CPG * NTOK;
    const float4* xv = (const float4*)(x + base);
    int tid = threadIdx.x;

    float s = 0.f, ss = 0.f;
#pragma unroll
    for (int r = 0; r < 8; r++) {
        float4 v = xv[tid + r * 512];
        s  += v.x + v.y + v.z + v.w;
        ss += v.x * v.x + v.y * v.y + v.z * v.z + v.w * v.w;
    }
    __shared__ float rs[16], rss[16];
#pragma unroll
    for (int o = 16; o; o >>= 1) {
        s  += __shfl_xor_sync(0xffffffffu, s, o);
        ss += __shfl_xor_sync(0xffffffffu, ss, o);
    }
    if ((tid & 31) == 0) { rs[tid >> 5] = s; rss[tid >> 5] = ss; }
    __syncthreads();
    if (tid == 0) {
        float ts = 0.f, tss = 0.f;
#pragma unroll
        for (int i = 0; i < 16; i++) { ts += rs[i]; tss += rss[i]; }
        const float invN = 1.f / (CPG * NTOK);
        float mean = ts * invN;
        float var  = tss * invN - mean * mean;
        g_stats[bg] = make_float2(mean, rsqrtf(var + GN_EPS));
    }
}

// ======================= K2: mega kernel, 128 threads, M=32 per warp =======================
#define PA_XS 0
#define PA_WS 34816
#define PA_STG 69632
#define KT 17408                               // K tile [64 key][136 bf16]
#define VT 18432                               // V^T tile [128 ch][72 bf16]
#define OFF_KB(i) ((i) * KT)
#define OFF_VB(i) (3 * KT + (i) * VT)
#define OFF_WO 17408                           // epilogue Wo image: KB(1)+KB(2)
#define ATTN_SMEM (3 * KT + 3 * VT)            // 107520 B -> 2 CTA/SM

__global__ __launch_bounds__(128, 2) void mega_kernel(
        const float* __restrict__ x,
        const float* __restrict__ gw, const float* __restrict__ gb,
        const float* __restrict__ bq, const float* __restrict__ bk,
        const float* __restrict__ bv, const float* __restrict__ bo,
        const float* __restrict__ gamma, float* __restrict__ out) {
    extern __shared__ char smem[];
    uint32_t sbase = smem_u32(smem);
    int tid = threadIdx.x;
    int w = tid >> 5, lid = tid & 31;
    int gr = lid >> 2, t = lid & 3;
    int r0 = w * 32;
    int b = blockIdx.y, n0 = blockIdx.x * 128;
    int own = blockIdx.x * 2;

    __nv_bfloat16* xs_h = (__nv_bfloat16*)(smem + PA_XS);
    uint4* ws_v4 = (uint4*)(smem + PA_WS);

    const __nv_bfloat16* kg = g_k + (size_t)b * NTOK * CH;
    const __nv_bfloat16* vg = g_v + (size_t)b * CH * NTOK;
    int kload_row = tid >> 4, kload_seg = tid & 15;
    int vload_row = tid >> 3, vload_seg = tid & 7;

    // ======== Phase A1: stage x-hat once + copy pre-packed Wk ========
#pragma unroll
    for (int r = 0; r < 32; r++) {
        int idx = tid + r * 128;
        int c = idx >> 5, seg = idx & 31;
        float4 v = *(const float4*)&x[((size_t)(b * CH + c)) * NTOK + n0 + seg * 4];
        float2 st = g_stats[b * NGRP + (c >> 2)];
        float a = gw[c] * st.y;
        float bb = gb[c] - st.x * a;
        int tok = seg * 4;
        xs_h[(tok + 0) * 136 + c] = __float2bfloat16(v.x * a + bb);
        xs_h[(tok + 1) * 136 + c] = __float2bfloat16(v.y * a + bb);
        xs_h[(tok + 2) * 136 + c] = __float2bfloat16(v.z * a + bb);
        xs_h[(tok + 3) * 136 + c] = __float2bfloat16(v.w * a + bb);
    }
#pragma unroll
    for (int r = 0; r < 17; r++) {
        int idx = tid + r * 128;
        ws_v4[idx] = ((const uint4*)g_wk_pk)[idx];
    }
    __syncthreads();

    uint32_t bbase = sbase + PA_XS + (uint32_t)(lid & 7) * 272 + (uint32_t)(lid >> 3) * 16;
    uint32_t abw0 = sbase + PA_WS + (uint32_t)(r0 + (lid & 15)) * 272 + (uint32_t)(lid >> 4) * 16;
    uint32_t abw1 = abw0 + 16 * 272;

    // ======== Phase A2: K projection ========
    {
        uint32_t af[2][8][4];
#pragma unroll
        for (int c = 0; c < 8; c++) {
            LDSM_X4(af[0][c][0], af[0][c][1], af[0][c][2], af[0][c][3], abw0 + c * 32);
            LDSM_X4(af[1][c][0], af[1][c][1], af[1][c][2], af[1][c][3], abw1 + c * 32);
        }
        float bs0 = bk[r0 + gr],      bs1 = bk[r0 + 8 + gr];
        float bs2 = bk[r0 + 16 + gr], bs3 = bk[r0 + 24 + gr];
        __nv_bfloat16* stg = (__nv_bfloat16*)(smem + PA_STG);
#pragma unroll 2
        for (int nb = 0; nb < 16; nb++) {
            float d0[4] = {0.f, 0.f, 0.f, 0.f};
            float d1[4] = {0.f, 0.f, 0.f, 0.f};
#pragma unroll
            for (int cp = 0; cp < 4; cp++) {
                uint32_t b0, b1, b2, b3;
                LDSM_X4(b0, b1, b2, b3, bbase + (uint32_t)nb * 2176 + cp * 64);
                mma_bf16(d0, af[0][2 * cp][0], af[0][2 * cp][1], af[0][2 * cp][2], af[0][2 * cp][3], b0, b1);
                mma_bf16(d1, af[1][2 * cp][0], af[1][2 * cp][1], af[1][2 * cp][2], af[1][2 * cp][3], b0, b1);
                mma_bf16(d0, af[0][2 * cp + 1][0], af[0][2 * cp + 1][1], af[0][2 * cp + 1][2], af[0][2 * cp + 1][3], b2, b3);
                mma_bf16(d1, af[1][2 * cp + 1][0], af[1][2 * cp + 1][1], af[1][2 * cp + 1][2], af[1][2 * cp + 1][3], b2, b3);
            }
            int tok = nb * 8 + 2 * t;
            stg[tok * 136 + r0 + gr]            = __float2bfloat16(d0[0] + bs0);
            stg[(tok + 1) * 136 + r0 + gr]      = __float2bfloat16(d0[1] + bs0);
            stg[tok * 136 + r0 + 8 + gr]        = __float2bfloat16(d0[2] + bs1);
            stg[(tok + 1) * 136 + r0 + 8 + gr]  = __float2bfloat16(d0[3] + bs1);
            stg[tok * 136 + r0 + 16 + gr]       = __float2bfloat16(d1[0] + bs2);
            stg[(tok + 1) * 136 + r0 + 16 + gr] = __float2bfloat16(d1[1] + bs2);
            stg[tok * 136 + r0 + 24 + gr]       = __float2bfloat16(d1[2] + bs3);
            stg[(tok + 1) * 136 + r0 + 24 + gr] = __float2bfloat16(d1[3] + bs3);
        }
        __syncthreads();
#pragma unroll
        for (int r = 0; r < 16; r++) {
            int idx = tid + r * 128;
            int tok = idx >> 4, seg = idx & 15;
            uint4 v = *(uint4*)(smem + PA_STG + tok * 272 + seg * 16);
            *(uint4*)((char*)g_k + ((size_t)b * NTOK + n0 + tok) * 256 + seg * 16) = v;
        }
#pragma unroll
        for (int r = 0; r < 17; r++) {
            int idx = tid + r * 128;
            ws_v4[idx] = ((const uint4*)g_wv_pk)[idx];
        }
        __syncthreads();
    }

    // ======== Phase A3: V projection ========
    {
        uint32_t af[2][8][4];
#pragma unroll
        for (int c = 0; c < 8; c++) {
            LDSM_X4(af[0][c][0], af[0][c][1], af[0][c][2], af[0][c][3], abw0 + c * 32);
            LDSM_X4(af[1][c][0], af[1][c][1], af[1][c][2], af[1][c][3], abw1 + c * 32);
        }
        float bs0 = bv[r0 + gr],      bs1 = bv[r0 + 8 + gr];
        float bs2 = bv[r0 + 16 + gr], bs3 = bv[r0 + 24 + gr];
        uint32_t* stg = (uint32_t*)(smem + PA_STG);
#pragma unroll 2
        for (int nb = 0; nb < 16; nb++) {
            float d0[4] = {0.f, 0.f, 0.f, 0.f};
            float d1[4] = {0.f, 0.f, 0.f, 0.f};
#pragma unroll
            for (int cp = 0; cp < 4; cp++) {
                uint32_t b0, b1, b2, b3;
                LDSM_X4(b0, b1, b2, b3, bbase + (uint32_t)nb * 2176 + cp * 64);
                mma_bf16(d0, af[0][2 * cp][0], af[0][2 * cp][1], af[0][2 * cp][2], af[0][2 * cp][3], b0, b1);
                mma_bf16(d1, af[1][2 * cp][0], af[1][2 * cp][1], af[1][2 * cp][2], af[1][2 * cp][3], b0, b1);
                mma_bf16(d0, af[0][2 * cp + 1][0], af[0][2 * cp + 1][1], af[0][2 * cp + 1][2], af[0][2 * cp + 1][3], b2, b3);
                mma_bf16(d1, af[1][2 * cp + 1][0], af[1][2 * cp + 1][1], af[1][2 * cp + 1][2], af[1][2 * cp + 1][3], b2, b3);
            }
            stg[(r0 + gr) * 68 + nb * 4 + t]      = pack_bf16x2(d0[0] + bs0, d0[1] + bs0);
            stg[(r0 + 8 + gr) * 68 + nb * 4 + t]  = pack_bf16x2(d0[2] + bs1, d0[3] + bs1);
            stg[(r0 + 16 + gr) * 68 + nb * 4 + t] = pack_bf16x2(d1[0] + bs2, d1[1] + bs2);
            stg[(r0 + 24 + gr) * 68 + nb * 4 + t] = pack_bf16x2(d1[2] + bs3, d1[3] + bs3);
        }
        __syncthreads();
#pragma unroll
        for (int r = 0; r < 16; r++) {
            int idx = tid + r * 128;
            int c = idx >> 4, seg = idx & 15;
            uint4 v = *(uint4*)(smem + PA_STG + c * 272 + seg * 16);
            *(uint4*)((char*)g_v + (((size_t)(b * CH + c)) * NTOK + n0) * 2 + seg * 16) = v;
        }
#pragma unroll
        for (int r = 0; r < 17; r++) {
            int idx = tid + r * 128;
            ws_v4[idx] = ((const uint4*)g_wq_pk)[idx];
        }
        __threadfence();
        __syncthreads();
        if (tid == 0) atomicAdd(&g_cnt[b], 1);
    }

    // ======== Phase A4: Q projection ========
    uint32_t qa[2][8][4];
    {
        uint32_t wqb = sbase + PA_WS + (uint32_t)(lid & 7) * 272 + (uint32_t)(lid >> 3) * 16;
#pragma unroll
        for (int blk = 0; blk < 2; blk++) {
            uint32_t xa[8][4];
            uint32_t abx = sbase + PA_XS + (uint32_t)(r0 + blk * 16 + (lid & 15)) * 272 + (uint32_t)(lid >> 4) * 16;
#pragma unroll
            for (int c = 0; c < 8; c++)
                LDSM_X4(xa[c][0], xa[c][1], xa[c][2], xa[c][3], abx + c * 32);
#pragma unroll
            for (int k = 0; k < 8; k++) {
#pragma unroll
                for (int half = 0; half < 2; half++) {
                    int nb = 2 * k + half;
                    float d[4] = {0.f, 0.f, 0.f, 0.f};
#pragma unroll
                    for (int cp = 0; cp < 4; cp++) {
                        uint32_t b0, b1, b2, b3;
                        LDSM_X4(b0, b1, b2, b3, wqb + (uint32_t)nb * 2176 + cp * 64);
                        mma_bf16(d, xa[2 * cp][0], xa[2 * cp][1], xa[2 * cp][2], xa[2 * cp][3], b0, b1);
                        mma_bf16(d, xa[2 * cp + 1][0], xa[2 * cp + 1][1], xa[2 * cp + 1][2], xa[2 * cp + 1][3], b2, b3);
                    }
                    float2 bq2 = *(const float2*)&bq[nb * 8 + 2 * t];
                    qa[blk][k][2 * half]     = pack_bf16x2((d[0] + bq2.x) * QK_SCALE_L2E, (d[1] + bq2.y) * QK_SCALE_L2E);
                    qa[blk][k][2 * half + 1] = pack_bf16x2((d[2] + bq2.x) * QK_SCALE_L2E, (d[3] + bq2.y) * QK_SCALE_L2E);
                }
            }
        }
    }

    // ======== Phase A5: wait for batch KV completion ========
    if (tid == 0) {
        while (atomicAdd(&g_cnt[b], 0) < NTOK / 128) { }
    }
    __syncthreads();

    // ======== ring prefetch: rotated start at own tiles ========
#pragma unroll
    for (int pt = 0; pt < 2; pt++) {
        int gt = own + pt;
        const char* kn = (const char*)kg + (size_t)gt * 64 * 256;
        const char* vn = (const char*)vg + (size_t)gt * 128;
        uint32_t koff = sbase + OFF_KB(pt);
        uint32_t voff = sbase + OFF_VB(pt);
#pragma unroll
        for (int r = 0; r < 8; r++) {
            int row = kload_row + r * 8;
            CP_ASYNC16(koff + row * 272 + kload_seg * 16, kn + row * 256 + kload_seg * 16);
        }
#pragma unroll
        for (int r = 0; r < 8; r++) {
            int row = vload_row + r * 16;
            CP_ASYNC16(voff + row * 144 + vload_seg * 16, vn + (size_t)row * NTOK * 2 + vload_seg * 16);
        }
        CP_COMMIT();
    }

    // ======== Phase B: flash attention mainloop ========
    float oacc[2][16][4];
#pragma unroll
    for (int blk = 0; blk < 2; blk++)
#pragma unroll
        for (int v = 0; v < 16; v++)
#pragma unroll
            for (int i = 0; i < 4; i++) oacc[blk][v][i] = 0.f;
    float l0[2] = {0.f, 0.f}, l1[2] = {0.f, 0.f};

    uint32_t klane = (uint32_t)(lid & 7) * 272 + (uint32_t)(lid >> 3) * 16;
    uint32_t vlane = (uint32_t)(lid & 7) * 144 + (uint32_t)(lid >> 3) * 16;

    // ring offsets as running registers (no per-tile select chains)
    uint32_t kcur = sbase + klane;                 // OFF_KB(0) + klane
    uint32_t vcur = sbase + 3 * KT + vlane;        // OFF_VB(0) + vlane
    uint32_t kpre = sbase + 2 * KT;                // OFF_KB(2)
    uint32_t vpre = sbase + 3 * KT + 2 * VT;       // OFF_VB(2)
    const uint32_t kcur_hi = sbase + klane + 3 * KT;
    const uint32_t vcur_hi = sbase + 3 * KT + vlane + 3 * VT;
    const uint32_t kpre_hi = sbase + 3 * KT;
    const uint32_t vpre_hi = sbase + 3 * KT + 3 * VT;

    for (int tl = 0; tl < NTOK / 64; tl++) {
        CP_WAIT1();
        __syncthreads();

        if (tl + 2 < NTOK / 64) {
            int gt2 = (own + tl + 2) & 63;
            const char* kn = (const char*)kg + (size_t)gt2 * 64 * 256;
            const char* vn = (const char*)vg + (size_t)gt2 * 128;
#pragma unroll
            for (int r = 0; r < 8; r++) {
                int row = kload_row + r * 8;
                CP_ASYNC16(kpre + row * 272 + kload_seg * 16, kn + row * 256 + kload_seg * 16);
            }
#pragma unroll
            for (int r = 0; r < 8; r++) {
                int row = vload_row + r * 16;
                CP_ASYNC16(vpre + row * 144 + vload_seg * 16, vn + (size_t)row * NTOK * 2 + vload_seg * 16);
            }
        } else if (tl == NTOK / 64 - 1) {
#pragma unroll
            for (int r = 0; r < 17; r++) {
                int idx = tid + r * 128;
                CP_ASYNC16(sbase + OFF_WO + idx * 16, (const char*)g_wo_pk + idx * 16);
            }
        }
        CP_COMMIT();

        uint32_t kb = kcur, vb = vcur;

#pragma unroll
        for (int half = 0; half < 2; half++) {
            uint32_t epk[2][4][2];
#pragma unroll
            for (int nn = 0; nn < 4; nn++) {
                int n = half * 4 + nn;
                float s0[4] = {0.f, 0.f, 0.f, 0.f};
                float s1[4] = {0.f, 0.f, 0.f, 0.f};
                uint32_t krow = kb + (uint32_t)n * 2176;
#pragma unroll
                for (int cp = 0; cp < 4; cp++) {
                    uint32_t b0, b1, b2, b3;
                    LDSM_X4(b0, b1, b2, b3, krow + cp * 64);
                    mma_bf16(s0, qa[0][2 * cp][0], qa[0][2 * cp][1], qa[0][2 * cp][2], qa[0][2 * cp][3], b0, b1);
                    mma_bf16(s1, qa[1][2 * cp][0], qa[1][2 * cp][1], qa[1][2 * cp][2], qa[1][2 * cp][3], b0, b1);
                    mma_bf16(s0, qa[0][2 * cp + 1][0], qa[0][2 * cp + 1][1], qa[0][2 * cp + 1][2], qa[0][2 * cp + 1][3], b2, b3);
                    mma_bf16(s1, qa[1][2 * cp + 1][0], qa[1][2 * cp + 1][1], qa[1][2 * cp + 1][2], qa[1][2 * cp + 1][3], b2, b3);
                }
                float e00 = ex2_fast(s0[0]), e01 = ex2_fast(s0[1]);
                float e02 = ex2_fast(s0[2]), e03 = ex2_fast(s0[3]);
                float e10 = ex2_fast(s1[0]), e11 = ex2_fast(s1[1]);
                float e12 = ex2_fast(s1[2]), e13 = ex2_fast(s1[3]);
                l0[0] += e00 + e01; l1[0] += e02 + e03;
                l0[1] += e10 + e11; l1[1] += e12 + e13;
                epk[0][nn][0] = pack_bf16x2(e00, e01);
                epk[0][nn][1] = pack_bf16x2(e02, e03);
                epk[1][nn][0] = pack_bf16x2(e10, e11);
                epk[1][nn][1] = pack_bf16x2(e12, e13);
            }
#pragma unroll
            for (int v = 0; v < 16; v++) {
                uint32_t b0, b1, b2, b3;
                LDSM_X4(b0, b1, b2, b3, vb + (uint32_t)v * 1152 + half * 64);
                mma_bf16(oacc[0][v], epk[0][0][0], epk[0][0][1], epk[0][1][0], epk[0][1][1], b0, b1);
                mma_bf16(oacc[1][v], epk[1][0][0], epk[1][0][1], epk[1][1][0], epk[1][1][1], b0, b1);
                mma_bf16(oacc[0][v], epk[0][2][0], epk[0][2][1], epk[0][3][0], epk[0][3][1], b2, b3);
                mma_bf16(oacc[1][v], epk[1][2][0], epk[1][2][1], epk[1][3][0], epk[1][3][1], b2, b3);
            }
        }

        // advance ring registers with wrap
        kcur += KT; if (kcur >= kcur_hi) kcur -= 3 * KT;
        vcur += VT; if (vcur >= vcur_hi) vcur -= 3 * VT;
        kpre += KT; if (kpre >= kpre_hi) kpre -= 3 * KT;
        vpre += VT; if (vpre >= vpre_hi) vpre -= 3 * VT;
    }

    // ---- row sums ----
#pragma unroll
    for (int blk = 0; blk < 2; blk++) {
        l0[blk] += __shfl_xor_sync(0xffffffffu, l0[blk], 1);
        l0[blk] += __shfl_xor_sync(0xffffffffu, l0[blk], 2);
        l1[blk] += __shfl_xor_sync(0xffffffffu, l1[blk], 1);
        l1[blk] += __shfl_xor_sync(0xffffffffu, l1[blk], 2);
    }

    // ======== fused output projection epilogue ========
    uint32_t af[2][8][4];
#pragma unroll
    for (int blk = 0; blk < 2; blk++) {
        float inv0 = 1.f / l0[blk], inv1 = 1.f / l1[blk];
#pragma unroll
        for (int cp = 0; cp < 8; cp++) {
            af[blk][cp][0] = pack_bf16x2(oacc[blk][2 * cp][0] * inv0,     oacc[blk][2 * cp][1] * inv0);
            af[blk][cp][1] = pack_bf16x2(oacc[blk][2 * cp][2] * inv1,     oacc[blk][2 * cp][3] * inv1);
            af[blk][cp][2] = pack_bf16x2(oacc[blk][2 * cp + 1][0] * inv0, oacc[blk][2 * cp + 1][1] * inv0);
            af[blk][cp][3] = pack_bf16x2(oacc[blk][2 * cp + 1][2] * inv1, oacc[blk][2 * cp + 1][3] * inv1);
        }
    }

    CP_WAIT0();
    __syncthreads();

    __nv_bfloat16* stg = (__nv_bfloat16*)(smem + OFF_VB(0));
    uint32_t wob = sbase + OFF_WO + klane;
#pragma unroll 2
    for (int nb = 0; nb < 16; nb++) {
        float d0[4] = {0.f, 0.f, 0.f, 0.f};
        float d1[4] = {0.f, 0.f, 0.f, 0.f};
#pragma unroll
        for (int cp = 0; cp < 4; cp++) {
            uint32_t b0, b1, b2, b3;
            LDSM_X4(b0, b1, b2, b3, wob + (uint32_t)nb * 2176 + cp * 64);
            mma_bf16(d0, af[0][2 * cp][0], af[0][2 * cp][1], af[0][2 * cp][2], af[0][2 * cp][3], b0, b1);
            mma_bf16(d1, af[1][2 * cp][0], af[1][2 * cp][1], af[1][2 * cp][2], af[1][2 * cp][3], b0, b1);
            mma_bf16(d0, af[0][2 * cp + 1][0], af[0][2 * cp + 1][1], af[0][2 * cp + 1][2], af[0][2 * cp + 1][3], b2, b3);
            mma_bf16(d1, af[1][2 * cp + 1][0], af[1][2 * cp + 1][1], af[1][2 * cp + 1][2], af[1][2 * cp + 1][3], b2, b3);
        }
        int o = nb * 8 + 2 * t;
        stg[o * 136 + r0 + gr]            = __float2bfloat16(d0[0]);
        stg[(o + 1) * 136 + r0 + gr]      = __float2bfloat16(d0[1]);
        stg[o * 136 + r0 + 8 + gr]        = __float2bfloat16(d0[2]);
        stg[(o + 1) * 136 + r0 + 8 + gr]  = __float2bfloat16(d0[3]);
        stg[o * 136 + r0 + 16 + gr]       = __float2bfloat16(d1[0]);
        stg[(o + 1) * 136 + r0 + 16 + gr] = __float2bfloat16(d1[1]);
        stg[o * 136 + r0 + 24 + gr]       = __float2bfloat16(d1[2]);
        stg[(o + 1) * 136 + r0 + 24 + gr] = __float2bfloat16(d1[3]);
    }
    __syncthreads();

    float gma = gamma[0];
#pragma unroll
    for (int r = 0; r < 16; r++) {
        int idx = tid + r * 128;
        int o = idx >> 4, seg = idx & 15;
        uint4 pv = *(uint4*)((char*)stg + o * 272 + seg * 16);
        float bv_ = bo[o];
        size_t gidx = ((size_t)(b * CH + o)) * NTOK + n0 + seg * 8;
        float4 x0 = *(const float4*)&x[gidx];
        float4 x1 = *(const float4*)&x[gidx + 4];
        float2 u0 = __bfloat1622float2(*(__nv_bfloat162*)&pv.x);
        float2 u1 = __bfloat1622float2(*(__nv_bfloat162*)&pv.y);
        float2 u2 = __bfloat1622float2(*(__nv_bfloat162*)&pv.z);
        float2 u3 = __bfloat1622float2(*(__nv_bfloat162*)&pv.w);
        float4 o0, o1;
        o0.x = x0.x + gma * (u0.x + bv_);
        o0.y = x0.y + gma * (u0.y + bv_);
        o0.z = x0.z + gma * (u1.x + bv_);
        o0.w = x0.w + gma * (u1.y + bv_);
        o1.x = x1.x + gma * (u2.x + bv_);
        o1.y = x1.y + gma * (u2.y + bv_);
        o1.z = x1.z + gma * (u3.x + bv_);
        o1.w = x1.w + gma * (u3.y + bv_);
        *(float4*)&out[gidx] = o0;
        *(float4*)&out[gidx + 4] = o1;
    }
}

// ======================= launch =======================
extern "C" void kernel_launch(void* const* d_in, const int* in_sizes, int n_in,
                              void* d_out, int out_size) {
    const float* x  = (const float*)d_in[0];
    const float* gw = (const float*)d_in[1];
    const float* gb = (const float*)d_in[2];
    const float* wq = (const float*)d_in[3];
    const float* bq = (const float*)d_in[4];
    const float* wk = (const float*)d_in[5];
    const float* bk = (const float*)d_in[6];
    const float* wv = (const float*)d_in[7];
    const float* bv = (const float*)d_in[8];
    const float* wo = (const float*)d_in[9];
    const float* bo = (const float*)d_in[10];
    const float* gamma = (const float*)d_in[11];
    float* out = (float*)d_out;

    static bool attr_set = false;
    if (!attr_set) {
        cudaFuncSetAttribute(mega_kernel, cudaFuncAttributeMaxDynamicSharedMemorySize, ATTN_SMEM);
        attr_set = true;
    }

    gn_stats_kernel<<<BATCH * NGRP + 4, 512>>>(x, wq, wk, wv, wo);
    mega_kernel<<<dim3(NTOK / 128, BATCH), 128, ATTN_SMEM>>>(
        x, gw, gb, bq, bk, bv, bo, gamma, out);
}

// round 17
// speedup vs baseline: 1.0305x; 1.0233x over previous
#include <cuda_runtime.h>
#include <cuda_bf16.h>
#include <math.h>
#include <stdint.h>

#define BATCH 8
#define CH 128
#define NTOK 4096
#define NGRP 32
#define CPG 4
#define GN_EPS 1e-5f
#define QK_SCALE_L2E 0.12751748754f   // log2(e)/sqrt(128)

// ---------------- scratch (device globals; no allocations) ----------------
__device__ float2 g_stats[BATCH * NGRP];             // (mean, rstd) per (b,g)
__device__ __nv_bfloat16 g_k[BATCH * NTOK * CH];     // (b,n,c) token-major
__device__ __nv_bfloat16 g_v[BATCH * CH * NTOK];     // (b,c,n) channel-major (V^T tiles)
__device__ int g_cnt[BATCH];                         // kv-done counters (zeroed by gn_stats)
// pre-packed weights, bf16 [o][136 halfwords] = 68 u32/row, 8704 u32 = 34816 B each
__device__ uint32_t g_wq_pk[8704];
__device__ uint32_t g_wk_pk[8704];
__device__ uint32_t g_wv_pk[8704];
__device__ uint32_t g_wo_pk[8704];

// ======================= helpers =======================
__device__ __forceinline__ uint32_t smem_u32(const void* p) {
    uint32_t a;
    asm("{ .reg .u64 t; cvta.to.shared.u64 t, %1; cvt.u32.u64 %0, t; }" : "=r"(a) : "l"(p));
    return a;
}
__device__ __forceinline__ uint32_t pack_bf16x2(float lo, float hi) {
    uint32_t r;
    asm("cvt.rn.bf16x2.f32 %0, %1, %2;" : "=r"(r) : "f"(hi), "f"(lo));
    return r;
}
__device__ __forceinline__ float ex2_fast(float x) {
    float r;
    asm("ex2.approx.ftz.f32 %0, %1;" : "=f"(r) : "f"(x));
    return r;
}
// D += A*B, m16n8k16, bf16 in / fp32 accum. NON-volatile: register deps enforce
// correctness; scheduler may interleave independent chains freely.
__device__ __forceinline__ void mma_bf16(float* d, uint32_t a0, uint32_t a1, uint32_t a2, uint32_t a3,
                                         uint32_t b0, uint32_t b1) {
    asm("mma.sync.aligned.m16n8k16.row.col.f32.bf16.bf16.f32 "
        "{%0,%1,%2,%3}, {%4,%5,%6,%7}, {%8,%9}, {%0,%1,%2,%3};"
        : "+f"(d[0]), "+f"(d[1]), "+f"(d[2]), "+f"(d[3])
        : "r"(a0), "r"(a1), "r"(a2), "r"(a3), "r"(b0), "r"(b1));
}
#define LDSM_X4(r0, r1, r2, r3, addr) \
    asm volatile("ldmatrix.sync.aligned.m8n8.x4.shared.b16 {%0,%1,%2,%3}, [%4];" \
                 : "=r"(r0), "=r"(r1), "=r"(r2), "=r"(r3) : "r"(addr))
#define CP_ASYNC16(dst_u32, src_ptr) \
    asm volatile("cp.async.cg.shared.global [%0], [%1], 16;" :: "r"(dst_u32), "l"(src_ptr))
#define CP_COMMIT()  asm volatile("cp.async.commit_group;" ::: "memory")
#define CP_WAIT1()   asm volatile("cp.async.wait_group 1;" ::: "memory")
#define CP_WAIT0()   asm volatile("cp.async.wait_group 0;" ::: "memory")

// ======================= K1: GroupNorm stats + counter reset + W packing =======================
__global__ __launch_bounds__(512) void gn_stats_kernel(const float* __restrict__ x,
                                                       const float* __restrict__ wq,
                                                       const float* __restrict__ wk,
                                                       const float* __restrict__ wv,
                                                       const float* __restrict__ wo) {
    int bg = blockIdx.x;
    if (bg >= BATCH * NGRP) {
        int which = bg - BATCH * NGRP;
        const float* W = (which == 0) ? wq : (which == 1) ? wk : (which == 2) ? wv : wo;
        uint32_t* dst = (which == 0) ? g_wq_pk : (which == 1) ? g_wk_pk : (which == 2) ? g_wv_pk : g_wo_pk;
#pragma unroll
        for (int r = 0; r < 17; r++) {
            int idx = threadIdx.x + r * 512;
            int o = idx / 68, s = idx % 68;
            dst[idx] = (s < 64) ? pack_bf16x2(W[o * 128 + 2 * s], W[o * 128 + 2 * s + 1]) : 0u;
        }
        return;
    }
    if (threadIdx.x == 0 && bg < BATCH) g_cnt[bg] = 0;
    size_t base = (size_t)bg * CPG * NTOK;
    const float4* xv = (const float4*)(x + base);
    int tid = threadIdx.x;

    float s = 0.f, ss = 0.f;
#pragma unroll
    for (int r = 0; r < 8; r++) {
        float4 v = xv[tid + r * 512];
        s  += v.x + v.y + v.z + v.w;
        ss += v.x * v.x + v.y * v.y + v.z * v.z + v.w * v.w;
    }
    __shared__ float rs[16], rss[16];
#pragma unroll
    for (int o = 16; o; o >>= 1) {
        s  += __shfl_xor_sync(0xffffffffu, s, o);
        ss += __shfl_xor_sync(0xffffffffu, ss, o);
    }
    if ((tid & 31) == 0) { rs[tid >> 5] = s; rss[tid >> 5] = ss; }
    __syncthreads();
    if (tid == 0) {
        float ts = 0.f, tss = 0.f;
#pragma unroll
        for (int i = 0; i < 16; i++) { ts += rs[i]; tss += rss[i]; }
        const float invN = 1.f / (CPG * NTOK);
        float mean = ts * invN;
        float var  = tss * invN - mean * mean;
        g_stats[bg] = make_float2(mean, rsqrtf(var + GN_EPS));
    }
}

// ======================= K2: mega kernel, 128 threads, M=32 per warp =======================
#define PA_XS 0
#define PA_WS 34816
#define PA_STG 69632
#define KT 17408                               // K tile [64 key][136 bf16]
#define VT 18432                               // V^T tile [128 ch][72 bf16]
#define OFF_KB(i) ((i) * KT)
#define OFF_VB(i) (3 * KT + (i) * VT)
#define OFF_WO 17408                           // epilogue Wo image: KB(1)+KB(2)
#define ATTN_SMEM (3 * KT + 3 * VT)            // 107520 B -> 2 CTA/SM

__global__ __launch_bounds__(128, 2) void mega_kernel(
        const float* __restrict__ x,
        const float* __restrict__ gw, const float* __restrict__ gb,
        const float* __restrict__ bq, const float* __restrict__ bk,
        const float* __restrict__ bv, const float* __restrict__ bo,
        const float* __restrict__ gamma, float* __restrict__ out) {
    extern __shared__ char smem[];
    uint32_t sbase = smem_u32(smem);
    int tid = threadIdx.x;
    int w = tid >> 5, lid = tid & 31;
    int gr = lid >> 2, t = lid & 3;
    int r0 = w * 32;
    int b = blockIdx.y, n0 = blockIdx.x * 128;
    int own = blockIdx.x * 2;

    __nv_bfloat16* xs_h = (__nv_bfloat16*)(smem + PA_XS);
    uint4* ws_v4 = (uint4*)(smem + PA_WS);

    const __nv_bfloat16* kg = g_k + (size_t)b * NTOK * CH;
    const __nv_bfloat16* vg = g_v + (size_t)b * CH * NTOK;
    int kload_row = tid >> 4, kload_seg = tid & 15;
    int vload_row = tid >> 3, vload_seg = tid & 7;

    // ======== Phase A1: stage x-hat once + copy pre-packed Wk ========
#pragma unroll
    for (int r = 0; r < 32; r++) {
        int idx = tid + r * 128;
        int c = idx >> 5, seg = idx & 31;
        float4 v = *(const float4*)&x[((size_t)(b * CH + c)) * NTOK + n0 + seg * 4];
        float2 st = g_stats[b * NGRP + (c >> 2)];
        float a = gw[c] * st.y;
        float bb = gb[c] - st.x * a;
        int tok = seg * 4;
        xs_h[(tok + 0) * 136 + c] = __float2bfloat16(v.x * a + bb);
        xs_h[(tok + 1) * 136 + c] = __float2bfloat16(v.y * a + bb);
        xs_h[(tok + 2) * 136 + c] = __float2bfloat16(v.z * a + bb);
        xs_h[(tok + 3) * 136 + c] = __float2bfloat16(v.w * a + bb);
    }
#pragma unroll
    for (int r = 0; r < 17; r++) {
        int idx = tid + r * 128;
        ws_v4[idx] = ((const uint4*)g_wk_pk)[idx];
    }
    __syncthreads();

    uint32_t bbase = sbase + PA_XS + (uint32_t)(lid & 7) * 272 + (uint32_t)(lid >> 3) * 16;
    uint32_t abw0 = sbase + PA_WS + (uint32_t)(r0 + (lid & 15)) * 272 + (uint32_t)(lid >> 4) * 16;
    uint32_t abw1 = abw0 + 16 * 272;

    // ======== Phase A2: K projection ========
    {
        uint32_t af[2][8][4];
#pragma unroll
        for (int c = 0; c < 8; c++) {
            LDSM_X4(af[0][c][0], af[0][c][1], af[0][c][2], af[0][c][3], abw0 + c * 32);
            LDSM_X4(af[1][c][0], af[1][c][1], af[1][c][2], af[1][c][3], abw1 + c * 32);
        }
        float bs0 = bk[r0 + gr],      bs1 = bk[r0 + 8 + gr];
        float bs2 = bk[r0 + 16 + gr], bs3 = bk[r0 + 24 + gr];
        __nv_bfloat16* stg = (__nv_bfloat16*)(smem + PA_STG);
#pragma unroll 2
        for (int nb = 0; nb < 16; nb++) {
            float d0[4] = {0.f, 0.f, 0.f, 0.f};
            float d1[4] = {0.f, 0.f, 0.f, 0.f};
#pragma unroll
            for (int cp = 0; cp < 4; cp++) {
                uint32_t b0, b1, b2, b3;
                LDSM_X4(b0, b1, b2, b3, bbase + (uint32_t)nb * 2176 + cp * 64);
                mma_bf16(d0, af[0][2 * cp][0], af[0][2 * cp][1], af[0][2 * cp][2], af[0][2 * cp][3], b0, b1);
                mma_bf16(d1, af[1][2 * cp][0], af[1][2 * cp][1], af[1][2 * cp][2], af[1][2 * cp][3], b0, b1);
                mma_bf16(d0, af[0][2 * cp + 1][0], af[0][2 * cp + 1][1], af[0][2 * cp + 1][2], af[0][2 * cp + 1][3], b2, b3);
                mma_bf16(d1, af[1][2 * cp + 1][0], af[1][2 * cp + 1][1], af[1][2 * cp + 1][2], af[1][2 * cp + 1][3], b2, b3);
            }
            int tok = nb * 8 + 2 * t;
            stg[tok * 136 + r0 + gr]            = __float2bfloat16(d0[0] + bs0);
            stg[(tok + 1) * 136 + r0 + gr]      = __float2bfloat16(d0[1] + bs0);
            stg[tok * 136 + r0 + 8 + gr]        = __float2bfloat16(d0[2] + bs1);
            stg[(tok + 1) * 136 + r0 + 8 + gr]  = __float2bfloat16(d0[3] + bs1);
            stg[tok * 136 + r0 + 16 + gr]       = __float2bfloat16(d1[0] + bs2);
            stg[(tok + 1) * 136 + r0 + 16 + gr] = __float2bfloat16(d1[1] + bs2);
            stg[tok * 136 + r0 + 24 + gr]       = __float2bfloat16(d1[2] + bs3);
            stg[(tok + 1) * 136 + r0 + 24 + gr] = __float2bfloat16(d1[3] + bs3);
        }
        __syncthreads();
#pragma unroll
        for (int r = 0; r < 16; r++) {
            int idx = tid + r * 128;
            int tok = idx >> 4, seg = idx & 15;
            uint4 v = *(uint4*)(smem + PA_STG + tok * 272 + seg * 16);
            *(uint4*)((char*)g_k + ((size_t)b * NTOK + n0 + tok) * 256 + seg * 16) = v;
        }
#pragma unroll
        for (int r = 0; r < 17; r++) {
            int idx = tid + r * 128;
            ws_v4[idx] = ((const uint4*)g_wv_pk)[idx];
        }
        __syncthreads();
    }

    // ======== Phase A3: V projection ========
    {
        uint32_t af[2][8][4];
#pragma unroll
        for (int c = 0; c < 8; c++) {
            LDSM_X4(af[0][c][0], af[0][c][1], af[0][c][2], af[0][c][3], abw0 + c * 32);
            LDSM_X4(af[1][c][0], af[1][c][1], af[1][c][2], af[1][c][3], abw1 + c * 32);
        }
        float bs0 = bv[r0 + gr],      bs1 = bv[r0 + 8 + gr];
        float bs2 = bv[r0 + 16 + gr], bs3 = bv[r0 + 24 + gr];
        uint32_t* stg = (uint32_t*)(smem + PA_STG);
#pragma unroll 2
        for (int nb = 0; nb < 16; nb++) {
            float d0[4] = {0.f, 0.f, 0.f, 0.f};
            float d1[4] = {0.f, 0.f, 0.f, 0.f};
#pragma unroll
            for (int cp = 0; cp < 4; cp++) {
                uint32_t b0, b1, b2, b3;
                LDSM_X4(b0, b1, b2, b3, bbase + (uint32_t)nb * 2176 + cp * 64);
                mma_bf16(d0, af[0][2 * cp][0], af[0][2 * cp][1], af[0][2 * cp][2], af[0][2 * cp][3], b0, b1);
                mma_bf16(d1, af[1][2 * cp][0], af[1][2 * cp][1], af[1][2 * cp][2], af[1][2 * cp][3], b0, b1);
                mma_bf16(d0, af[0][2 * cp + 1][0], af[0][2 * cp + 1][1], af[0][2 * cp + 1][2], af[0][2 * cp + 1][3], b2, b3);
                mma_bf16(d1, af[1][2 * cp + 1][0], af[1][2 * cp + 1][1], af[1][2 * cp + 1][2], af[1][2 * cp + 1][3], b2, b3);
            }
            stg[(r0 + gr) * 68 + nb * 4 + t]      = pack_bf16x2(d0[0] + bs0, d0[1] + bs0);
            stg[(r0 + 8 + gr) * 68 + nb * 4 + t]  = pack_bf16x2(d0[2] + bs1, d0[3] + bs1);
            stg[(r0 + 16 + gr) * 68 + nb * 4 + t] = pack_bf16x2(d1[0] + bs2, d1[1] + bs2);
            stg[(r0 + 24 + gr) * 68 + nb * 4 + t] = pack_bf16x2(d1[2] + bs3, d1[3] + bs3);
        }
        __syncthreads();
#pragma unroll
        for (int r = 0; r < 16; r++) {
            int idx = tid + r * 128;
            int c = idx >> 4, seg = idx & 15;
            uint4 v = *(uint4*)(smem + PA_STG + c * 272 + seg * 16);
            *(uint4*)((char*)g_v + (((size_t)(b * CH + c)) * NTOK + n0) * 2 + seg * 16) = v;
        }
#pragma unroll
        for (int r = 0; r < 17; r++) {
            int idx = tid + r * 128;
            ws_v4[idx] = ((const uint4*)g_wq_pk)[idx];
        }
        __threadfence();
        __syncthreads();
        if (tid == 0) atomicAdd(&g_cnt[b], 1);
    }

    // ======== Phase A4: Q projection ========
    uint32_t qa[2][8][4];
    {
        uint32_t wqb = sbase + PA_WS + (uint32_t)(lid & 7) * 272 + (uint32_t)(lid >> 3) * 16;
#pragma unroll
        for (int blk = 0; blk < 2; blk++) {
            uint32_t xa[8][4];
            uint32_t abx = sbase + PA_XS + (uint32_t)(r0 + blk * 16 + (lid & 15)) * 272 + (uint32_t)(lid >> 4) * 16;
#pragma unroll
            for (int c = 0; c < 8; c++)
                LDSM_X4(xa[c][0], xa[c][1], xa[c][2], xa[c][3], abx + c * 32);
#pragma unroll
            for (int k = 0; k < 8; k++) {
#pragma unroll
                for (int half = 0; half < 2; half++) {
                    int nb = 2 * k + half;
                    float d[4] = {0.f, 0.f, 0.f, 0.f};
#pragma unroll
                    for (int cp = 0; cp < 4; cp++) {
                        uint32_t b0, b1, b2, b3;
                        LDSM_X4(b0, b1, b2, b3, wqb + (uint32_t)nb * 2176 + cp * 64);
                        mma_bf16(d, xa[2 * cp][0], xa[2 * cp][1], xa[2 * cp][2], xa[2 * cp][3], b0, b1);
                        mma_bf16(d, xa[2 * cp + 1][0], xa[2 * cp + 1][1], xa[2 * cp + 1][2], xa[2 * cp + 1][3], b2, b3);
                    }
                    float2 bq2 = *(const float2*)&bq[nb * 8 + 2 * t];
                    qa[blk][k][2 * half]     = pack_bf16x2((d[0] + bq2.x) * QK_SCALE_L2E, (d[1] + bq2.y) * QK_SCALE_L2E);
                    qa[blk][k][2 * half + 1] = pack_bf16x2((d[2] + bq2.x) * QK_SCALE_L2E, (d[3] + bq2.y) * QK_SCALE_L2E);
                }
            }
        }
    }

    // ======== Phase A5: wait for batch KV completion ========
    if (tid == 0) {
        while (atomicAdd(&g_cnt[b], 0) < NTOK / 128) { }
    }
    __syncthreads();

    // ======== ring prefetch: rotated start at own tiles ========
#pragma unroll
    for (int pt = 0; pt < 2; pt++) {
        int gt = own + pt;
        const char* kn = (const char*)kg + (size_t)gt * 64 * 256;
        const char* vn = (const char*)vg + (size_t)gt * 128;
        uint32_t koff = sbase + OFF_KB(pt);
        uint32_t voff = sbase + OFF_VB(pt);
#pragma unroll
        for (int r = 0; r < 8; r++) {
            int row = kload_row + r * 8;
            CP_ASYNC16(koff + row * 272 + kload_seg * 16, kn + row * 256 + kload_seg * 16);
        }
#pragma unroll
        for (int r = 0; r < 8; r++) {
            int row = vload_row + r * 16;
            CP_ASYNC16(voff + row * 144 + vload_seg * 16, vn + (size_t)row * NTOK * 2 + vload_seg * 16);
        }
        CP_COMMIT();
    }

    // ======== Phase B: flash attention mainloop ========
    float oacc[2][16][4];
#pragma unroll
    for (int blk = 0; blk < 2; blk++)
#pragma unroll
        for (int v = 0; v < 16; v++)
#pragma unroll
            for (int i = 0; i < 4; i++) oacc[blk][v][i] = 0.f;
    float l0[2] = {0.f, 0.f}, l1[2] = {0.f, 0.f};

    uint32_t klane = (uint32_t)(lid & 7) * 272 + (uint32_t)(lid >> 3) * 16;
    uint32_t vlane = (uint32_t)(lid & 7) * 144 + (uint32_t)(lid >> 3) * 16;

    uint32_t kcur = sbase + klane;
    uint32_t vcur = sbase + 3 * KT + vlane;
    uint32_t kpre = sbase + 2 * KT;
    uint32_t vpre = sbase + 3 * KT + 2 * VT;
    const uint32_t kcur_hi = sbase + klane + 3 * KT;
    const uint32_t vcur_hi = sbase + 3 * KT + vlane + 3 * VT;
    const uint32_t kpre_hi = sbase + 3 * KT;
    const uint32_t vpre_hi = sbase + 3 * KT + 3 * VT;

    for (int tl = 0; tl < NTOK / 64; tl++) {
        CP_WAIT1();
        __syncthreads();

        if (tl + 2 < NTOK / 64) {
            int gt2 = (own + tl + 2) & 63;
            const char* kn = (const char*)kg + (size_t)gt2 * 64 * 256;
            const char* vn = (const char*)vg + (size_t)gt2 * 128;
#pragma unroll
            for (int r = 0; r < 8; r++) {
                int row = kload_row + r * 8;
                CP_ASYNC16(kpre + row * 272 + kload_seg * 16, kn + row * 256 + kload_seg * 16);
            }
#pragma unroll
            for (int r = 0; r < 8; r++) {
                int row = vload_row + r * 16;
                CP_ASYNC16(vpre + row * 144 + vload_seg * 16, vn + (size_t)row * NTOK * 2 + vload_seg * 16);
            }
        } else if (tl == NTOK / 64 - 1) {
#pragma unroll
            for (int r = 0; r < 17; r++) {
                int idx = tid + r * 128;
                CP_ASYNC16(sbase + OFF_WO + idx * 16, (const char*)g_wo_pk + idx * 16);
            }
        }
        CP_COMMIT();

        uint32_t kb = kcur, vb = vcur;

#pragma unroll
        for (int half = 0; half < 2; half++) {
            uint32_t epk[2][4][2];
#pragma unroll
            for (int nn = 0; nn < 4; nn++) {
                int n = half * 4 + nn;
                float s0[4] = {0.f, 0.f, 0.f, 0.f};
                float s1[4] = {0.f, 0.f, 0.f, 0.f};
                uint32_t krow = kb + (uint32_t)n * 2176;
                // LDSM double buffer: prefetch cp+1 before cp's MMAs
                uint32_t kbf[2][4];
                LDSM_X4(kbf[0][0], kbf[0][1], kbf[0][2], kbf[0][3], krow);
#pragma unroll
                for (int cp = 0; cp < 4; cp++) {
                    if (cp < 3)
                        LDSM_X4(kbf[(cp + 1) & 1][0], kbf[(cp + 1) & 1][1],
                                kbf[(cp + 1) & 1][2], kbf[(cp + 1) & 1][3], krow + (cp + 1) * 64);
                    uint32_t b0 = kbf[cp & 1][0], b1 = kbf[cp & 1][1];
                    uint32_t b2 = kbf[cp & 1][2], b3 = kbf[cp & 1][3];
                    mma_bf16(s0, qa[0][2 * cp][0], qa[0][2 * cp][1], qa[0][2 * cp][2], qa[0][2 * cp][3], b0, b1);
                    mma_bf16(s1, qa[1][2 * cp][0], qa[1][2 * cp][1], qa[1][2 * cp][2], qa[1][2 * cp][3], b0, b1);
                    mma_bf16(s0, qa[0][2 * cp + 1][0], qa[0][2 * cp + 1][1], qa[0][2 * cp + 1][2], qa[0][2 * cp + 1][3], b2, b3);
                    mma_bf16(s1, qa[1][2 * cp + 1][0], qa[1][2 * cp + 1][1], qa[1][2 * cp + 1][2], qa[1][2 * cp + 1][3], b2, b3);
                }
                float e00 = ex2_fast(s0[0]), e01 = ex2_fast(s0[1]);
                float e02 = ex2_fast(s0[2]), e03 = ex2_fast(s0[3]);
                float e10 = ex2_fast(s1[0]), e11 = ex2_fast(s1[1]);
                float e12 = ex2_fast(s1[2]), e13 = ex2_fast(s1[3]);
                l0[0] += e00 + e01; l1[0] += e02 + e03;
                l0[1] += e10 + e11; l1[1] += e12 + e13;
                epk[0][nn][0] = pack_bf16x2(e00, e01);
                epk[0][nn][1] = pack_bf16x2(e02, e03);
                epk[1][nn][0] = pack_bf16x2(e10, e11);
                epk[1][nn][1] = pack_bf16x2(e12, e13);
            }
            {
                // PV with LDSM double buffer
                uint32_t vbf[2][4];
                LDSM_X4(vbf[0][0], vbf[0][1], vbf[0][2], vbf[0][3], vb + half * 64);
#pragma unroll
                for (int v = 0; v < 16; v++) {
                    if (v < 15)
                        LDSM_X4(vbf[(v + 1) & 1][0], vbf[(v + 1) & 1][1],
                                vbf[(v + 1) & 1][2], vbf[(v + 1) & 1][3],
                                vb + (uint32_t)(v + 1) * 1152 + half * 64);
                    uint32_t b0 = vbf[v & 1][0], b1 = vbf[v & 1][1];
                    uint32_t b2 = vbf[v & 1][2], b3 = vbf[v & 1][3];
                    mma_bf16(oacc[0][v], epk[0][0][0], epk[0][0][1], epk[0][1][0], epk[0][1][1], b0, b1);
                    mma_bf16(oacc[1][v], epk[1][0][0], epk[1][0][1], epk[1][1][0], epk[1][1][1], b0, b1);
                    mma_bf16(oacc[0][v], epk[0][2][0], epk[0][2][1], epk[0][3][0], epk[0][3][1], b2, b3);
                    mma_bf16(oacc[1][v], epk[1][2][0], epk[1][2][1], epk[1][3][0], epk[1][3][1], b2, b3);
                }
            }
        }

        kcur += KT; if (kcur >= kcur_hi) kcur -= 3 * KT;
        vcur += VT; if (vcur >= vcur_hi) vcur -= 3 * VT;
        kpre += KT; if (kpre >= kpre_hi) kpre -= 3 * KT;
        vpre += VT; if (vpre >= vpre_hi) vpre -= 3 * VT;
    }

    // ---- row sums ----
#pragma unroll
    for (int blk = 0; blk < 2; blk++) {
        l0[blk] += __shfl_xor_sync(0xffffffffu, l0[blk], 1);
        l0[blk] += __shfl_xor_sync(0xffffffffu, l0[blk], 2);
        l1[blk] += __shfl_xor_sync(0xffffffffu, l1[blk], 1);
        l1[blk] += __shfl_xor_sync(0xffffffffu, l1[blk], 2);
    }

    // ======== fused output projection epilogue ========
    uint32_t af[2][8][4];
#pragma unroll
    for (int blk = 0; blk < 2; blk++) {
        float inv0 = 1.f / l0[blk], inv1 = 1.f / l1[blk];
#pragma unroll
        for (int cp = 0; cp < 8; cp++) {
            af[blk][cp][0] = pack_bf16x2(oacc[blk][2 * cp][0] * inv0,     oacc[blk][2 * cp][1] * inv0);
            af[blk][cp][1] = pack_bf16x2(oacc[blk][2 * cp][2] * inv1,     oacc[blk][2 * cp][3] * inv1);
            af[blk][cp][2] = pack_bf16x2(oacc[blk][2 * cp + 1][0] * inv0, oacc[blk][2 * cp + 1][1] * inv0);
            af[blk][cp][3] = pack_bf16x2(oacc[blk][2 * cp + 1][2] * inv1, oacc[blk][2 * cp + 1][3] * inv1);
        }
    }

    CP_WAIT0();
    __syncthreads();

    __nv_bfloat16* stg = (__nv_bfloat16*)(smem + OFF_VB(0));
    uint32_t wob = sbase + OFF_WO + klane;
#pragma unroll 2
    for (int nb = 0; nb < 16; nb++) {
        float d0[4] = {0.f, 0.f, 0.f, 0.f};
        float d1[4] = {0.f, 0.f, 0.f, 0.f};
#pragma unroll
        for (int cp = 0; cp < 4; cp++) {
            uint32_t b0, b1, b2, b3;
            LDSM_X4(b0, b1, b2, b3, wob + (uint32_t)nb * 2176 + cp * 64);
            mma_bf16(d0, af[0][2 * cp][0], af[0][2 * cp][1], af[0][2 * cp][2], af[0][2 * cp][3], b0, b1);
            mma_bf16(d1, af[1][2 * cp][0], af[1][2 * cp][1], af[1][2 * cp][2], af[1][2 * cp][3], b0, b1);
            mma_bf16(d0, af[0][2 * cp + 1][0], af[0][2 * cp + 1][1], af[0][2 * cp + 1][2], af[0][2 * cp + 1][3], b2, b3);
            mma_bf16(d1, af[1][2 * cp + 1][0], af[1][2 * cp + 1][1], af[1][2 * cp + 1][2], af[1][2 * cp + 1][3], b2, b3);
        }
        int o = nb * 8 + 2 * t;
        stg[o * 136 + r0 + gr]            = __float2bfloat16(d0[0]);
        stg[(o + 1) * 136 + r0 + gr]      = __float2bfloat16(d0[1]);
        stg[o * 136 + r0 + 8 + gr]        = __float2bfloat16(d0[2]);
        stg[(o + 1) * 136 + r0 + 8 + gr]  = __float2bfloat16(d0[3]);
        stg[o * 136 + r0 + 16 + gr]       = __float2bfloat16(d1[0]);
        stg[(o + 1) * 136 + r0 + 16 + gr] = __float2bfloat16(d1[1]);
        stg[o * 136 + r0 + 24 + gr]       = __float2bfloat16(d1[2]);
        stg[(o + 1) * 136 + r0 + 24 + gr] = __float2bfloat16(d1[3]);
    }
    __syncthreads();

    float gma = gamma[0];
#pragma unroll
    for (int r = 0; r < 16; r++) {
        int idx = tid + r * 128;
        int o = idx >> 4, seg = idx & 15;
        uint4 pv = *(uint4*)((char*)stg + o * 272 + seg * 16);
        float bv_ = bo[o];
        size_t gidx = ((size_t)(b * CH + o)) * NTOK + n0 + seg * 8;
        float4 x0 = *(const float4*)&x[gidx];
        float4 x1 = *(const float4*)&x[gidx + 4];
        float2 u0 = __bfloat1622float2(*(__nv_bfloat162*)&pv.x);
        float2 u1 = __bfloat1622float2(*(__nv_bfloat162*)&pv.y);
        float2 u2 = __bfloat1622float2(*(__nv_bfloat162*)&pv.z);
        float2 u3 = __bfloat1622float2(*(__nv_bfloat162*)&pv.w);
        float4 o0, o1;
        o0.x = x0.x + gma * (u0.x + bv_);
        o0.y = x0.y + gma * (u0.y + bv_);
        o0.z = x0.z + gma * (u1.x + bv_);
        o0.w = x0.w + gma * (u1.y + bv_);
        o1.x = x1.x + gma * (u2.x + bv_);
        o1.y = x1.y + gma * (u2.y + bv_);
        o1.z = x1.z + gma * (u3.x + bv_);
        o1.w = x1.w + gma * (u3.y + bv_);
        *(float4*)&out[gidx] = o0;
        *(float4*)&out[gidx + 4] = o1;
    }
}

// ======================= launch =======================
extern "C" void kernel_launch(void* const* d_in, const int* in_sizes, int n_in,
                              void* d_out, int out_size) {
    const float* x  = (const float*)d_in[0];
    const float* gw = (const float*)d_in[1];
    const float* gb = (const float*)d_in[2];
    const float* wq = (const float*)d_in[3];
    const float* bq = (const float*)d_in[4];
    const float* wk = (const float*)d_in[5];
    const float* bk = (const float*)d_in[6];
    const float* wv = (const float*)d_in[7];
    const float* bv = (const float*)d_in[8];
    const float* wo = (const float*)d_in[9];
    const float* bo = (const float*)d_in[10];
    const float* gamma = (const float*)d_in[11];
    float* out = (float*)d_out;

    static bool attr_set = false;
    if (!attr_set) {
        cudaFuncSetAttribute(mega_kernel, cudaFuncAttributeMaxDynamicSharedMemorySize, ATTN_SMEM);
        attr_set = true;
    }

    gn_stats_kernel<<<BATCH * NGRP + 4, 512>>>(x, wq, wk, wv, wo);
    mega_kernel<<<dim3(NTOK / 128, BATCH), 128, ATTN_SMEM>>>(
        x, gw, gb, bq, bk, bv, bo, gamma, out);
}